// round 16
// baseline (speedup 1.0000x reference)
#include <cuda_runtime.h>
#include <cuda_bf16.h>
#include <cstdint>
#include <cstddef>

// ---------------------------------------------------------------------------
// LSTM T=512 B=64 I=H=512 on sm_103 (no tcgen05): mma.sync bf16 hi/lo split.
//   cvt2: x -> fragment-ordered bf16 hi/lo images g_ximg[t][bh]
//   rec:  persistent 128-CTA kernel. Per step: X-part MMA from a warp-private
//         cp.async-prefetched SMEM slice -> per-warp fine-grained wait ->
//         H-part MMA -> parity-buffered epilogue -> register activation ->
//         per-warp publish + release (no trailing CTA barrier).
// ---------------------------------------------------------------------------

#define T_STEPS 512
#define BATCH   64
#define HID     512

// fragment-ordered x image: [t][bh][16384 words]
__device__ __align__(16) uint32_t g_ximg[T_STEPS][2][16384];
// fragment-ordered h image: [parity][bh][16384 words]
__device__ __align__(16) uint32_t g_img[2][2][16384];
// fine-grained counters: [bh][k-group], 128B apart. 64 arrivals per step each.
__device__ __align__(16) unsigned long long g_barw[2][8][16];

#define REC_NCTA 128

// ------------------------------ helpers ------------------------------------
__device__ __forceinline__ unsigned long long ld_vol_u64(const unsigned long long* p) {
    unsigned long long v;
    asm volatile("ld.volatile.global.u64 %0, [%1];" : "=l"(v) : "l"(p));
    return v;
}
__device__ __forceinline__ unsigned long long ld_acq_u64(const unsigned long long* p) {
    unsigned long long v;
    asm volatile("ld.acquire.gpu.global.u64 %0, [%1];" : "=l"(v) : "l"(p));
    return v;
}
__device__ __forceinline__ void red_add_release(unsigned long long* p, unsigned long long v) {
    asm volatile("red.release.gpu.global.add.u64 [%0], %1;" :: "l"(p), "l"(v) : "memory");
}
__device__ __forceinline__ uint4 ldcg_u4(const uint32_t* p) {
    uint4 v;
    asm volatile("ld.global.cg.v4.u32 {%0,%1,%2,%3}, [%4];"
                 : "=r"(v.x), "=r"(v.y), "=r"(v.z), "=r"(v.w) : "l"(p));
    return v;
}
__device__ __forceinline__ uint4 lds_u4(uint32_t saddr) {
    uint4 v;
    asm volatile("ld.shared.v4.u32 {%0,%1,%2,%3}, [%4];"
                 : "=r"(v.x), "=r"(v.y), "=r"(v.z), "=r"(v.w) : "r"(saddr));
    return v;
}
__device__ __forceinline__ void ldsm_x4(uint32_t (&r)[4], uint32_t saddr) {
    asm volatile("ldmatrix.sync.aligned.m8n8.x4.shared.b16 {%0,%1,%2,%3}, [%4];"
                 : "=r"(r[0]), "=r"(r[1]), "=r"(r[2]), "=r"(r[3]) : "r"(saddr));
}
__device__ __forceinline__ void mma_bf16(float (&d)[4], const uint32_t (&a)[4],
                                         const uint32_t (&b)[2]) {
    asm volatile(
        "mma.sync.aligned.m16n8k16.row.col.f32.bf16.bf16.f32 "
        "{%0,%1,%2,%3}, {%4,%5,%6,%7}, {%8,%9}, {%0,%1,%2,%3};\n"
        : "+f"(d[0]), "+f"(d[1]), "+f"(d[2]), "+f"(d[3])
        : "r"(a[0]), "r"(a[1]), "r"(a[2]), "r"(a[3]), "r"(b[0]), "r"(b[1]));
}
__device__ __forceinline__ uint32_t pack_hi2(float2 v) {
    union { __nv_bfloat162 h2; uint32_t u; } r;
    r.h2.x = __float2bfloat16(v.x);
    r.h2.y = __float2bfloat16(v.y);
    return r.u;
}
__device__ __forceinline__ uint32_t pack_lo2(float2 v) {
    union { __nv_bfloat162 h2; uint32_t u; } r;
    __nv_bfloat16 hx = __float2bfloat16(v.x);
    __nv_bfloat16 hy = __float2bfloat16(v.y);
    r.h2.x = __float2bfloat16(v.x - __bfloat162float(hx));
    r.h2.y = __float2bfloat16(v.y - __bfloat162float(hy));
    return r.u;
}
__device__ __forceinline__ float fast_sigmoid(float x) { return 1.f / (1.f + __expf(-x)); }
__device__ __forceinline__ float fast_tanh(float x) {
    float ax = fabsf(x);
    float t = 1.f - 2.f / (__expf(2.f * ax) + 1.f);
    return copysignf(t, x);
}

// ===========================================================================
// cvt2: x -> fragment-ordered bf16 hi/lo image per (t, bh).  (proven mapping)
// ===========================================================================
__global__ void cvt2_kernel(const float* __restrict__ x) {
    const size_t gid = (size_t)blockIdx.x * 256 + threadIdx.x;  // 8388608 total
    const int w  = (int)(gid & 8191);
    const int bh = (int)((gid >> 13) & 1);
    const int t  = (int)(gid >> 14);
    const int j = w & 3, lane = (w >> 2) & 31, q = (w >> 7) & 1;
    const int kc = (w >> 8) & 3, wk = w >> 10;
    const int ni = 2 * q + (j >> 1), reg = j & 1;
    const int n = ni * 8 + (lane >> 2);
    const int k = wk * 64 + kc * 16 + reg * 8 + (lane & 3) * 2;
    float2 v = __ldg((const float2*)(x + ((size_t)t * 64 + bh * 32 + n) * 512 + k));
    const uint32_t blk = (uint32_t)(wk * 4 + kc) * 2;
    const uint32_t word = blk * 256u + (uint32_t)q * 128u + (uint32_t)lane * 4u + (uint32_t)j;
    g_ximg[t][bh][word]        = pack_hi2(v);   // part 0 (hi)
    g_ximg[t][bh][word + 256]  = pack_lo2(v);   // part 1 (lo) at blk+1
}

// ===========================================================================
// rec: 128 CTAs = 64 col-groups x 2 batch-halves, 256 thr, persistent.
// SMEM: Xbuf (64KB, warp-private 8KB slices, cp.async prefetched) |
//       W_ih hi/lo (ldsm tiles) | Pb[2] parity partial buffers | bias.
// ===========================================================================
#define SROW     1040
#define OFF_XBUF 0            // 65536 B (8 warps x 8192)
#define OFF_WIHH 65536        // 33280
#define OFF_WIHL 98816        // 33280
#define OFF_P    132096       // 2 x 34816 = 69632
#define OFF_BIAS 201728       // 128
#define SMEM2    201856

__global__ void __launch_bounds__(256, 1)
rec_kernel(const float* __restrict__ W_ih, const float* __restrict__ W_hh,
           const float* __restrict__ b_ih, const float* __restrict__ b_hh,
           float* __restrict__ ys) {
    extern __shared__ char smc[];
    const int tid = threadIdx.x;
    const int cg = blockIdx.x >> 1, bh = blockIdx.x & 1;
    const int warp = tid >> 5, lane = tid & 31;
    const int g = lane >> 2, tq = lane & 3;

    float* bias_s = (float*)(smc + OFF_BIAS);

    // per-warp consumer counter + replay-safe base (read before any arrival)
    const unsigned long long* wcnt = &g_barw[bh][warp][0];
    const unsigned long long wbase = ld_vol_u64(wcnt);
    // producer counter for this CTA's k-group
    unsigned long long* pcnt = &g_barw[bh][cg >> 3][0];

    if (tid < 32) {
        const int grow = (tid >> 3) * HID + cg * 8 + (tid & 7);
        bias_s[tid] = __ldg(b_ih + grow) + __ldg(b_hh + grow);
    }

    // ---- W_ih hi/lo -> SMEM, packed row order ----
    for (int i = tid; i < 32 * 256; i += 256) {
        const int r = i >> 8;
        const int kk = (i & 255) * 2;
        const int grow = (r >> 3) * HID + cg * 8 + (r & 7);
        float2 v = __ldg((const float2*)(W_ih + (size_t)grow * HID + kk));
        *(uint32_t*)(smc + OFF_WIHH + r * SROW + kk * 2) = pack_hi2(v);
        *(uint32_t*)(smc + OFF_WIHL + r * SROW + kk * 2) = pack_lo2(v);
    }

    // ---- W_hh fragments -> registers (once) ----
    const int k0 = warp * 64;
    uint32_t aH[4][2][4], aL[4][2][4];
    #pragma unroll
    for (int kc = 0; kc < 4; kc++) {
        const int k = k0 + kc * 16 + 2 * tq;
        #pragma unroll
        for (int mi = 0; mi < 2; mi++) {
            #pragma unroll
            for (int rr = 0; rr < 2; rr++) {
                const int row = mi * 16 + g + rr * 8;
                const int grow = (row >> 3) * HID + cg * 8 + (row & 7);
                float2 v0 = __ldg((const float2*)(W_hh + (size_t)grow * HID + k));
                float2 v1 = __ldg((const float2*)(W_hh + (size_t)grow * HID + k + 8));
                aH[kc][mi][rr]     = pack_hi2(v0);
                aH[kc][mi][2 + rr] = pack_hi2(v1);
                aL[kc][mi][rr]     = pack_lo2(v0);
                aL[kc][mi][2 + rr] = pack_lo2(v1);
            }
        }
    }
    __syncthreads();

    // ldsm offsets into the W_ih tile (bytes, incl warp k base)
    const int lq = lane & 7;
    const int qa_r = ((lane >> 3) & 1) * 8;
    const int qa_c = ((lane >> 4) & 1) * 16;
    const uint32_t sWihH = (uint32_t)__cvta_generic_to_shared(smc + OFF_WIHH);
    const uint32_t sWihL = (uint32_t)__cvta_generic_to_shared(smc + OFF_WIHL);
    uint32_t aOffX[2];
    #pragma unroll
    for (int mi = 0; mi < 2; mi++)
        aOffX[mi] = (uint32_t)((mi * 16 + lq + qa_r) * SROW + qa_c + k0 * 2);

    // Xbuf slice for this warp (smem addresses)
    const uint32_t sXbuf = (uint32_t)__cvta_generic_to_shared(smc + OFF_XBUF)
                         + (uint32_t)warp * 8192u;

    // issue cp.async prefetch of this warp's xim slice for step t
    auto xprefetch = [&](int t) {
        const uint32_t* src = &g_ximg[t][bh][(size_t)warp * 2048 + lane * 4];
        #pragma unroll
        for (int i = 0; i < 16; i++) {
            asm volatile("cp.async.cg.shared.global [%0], [%1], 16;\n"
                         :: "r"(sXbuf + (uint32_t)(i * 128 + lane * 4) * 4u),
                            "l"(src + i * 128));
        }
        asm volatile("cp.async.commit_group;\n" ::: "memory");
    };

    // activation identity: one (cc, bb) per thread, ys-coalesced order
    const int cc = tid & 7;
    const int bb = tid >> 3;
    float cst = 0.f;

    // publish word (part = tid parity: even=hi, odd=lo)
    uint32_t pub_word;
    {
        const int part = tid & 1;
        const int cp = cc >> 1;
        const uint32_t blk = (uint32_t)(((cg >> 3) * 4 + ((cg & 7) >> 1)) * 2 + part);
        pub_word = blk * 256u + (uint32_t)(bb >> 4) * 128u
                 + (uint32_t)((bb & 7) * 4 + cp) * 4u
                 + (uint32_t)(2 * ((bb >> 3) & 1) + (cg & 1));
    }

    xprefetch(0);

    for (int t = 0; t < T_STEPS; t++) {
        float acc[2][4][4];
        #pragma unroll
        for (int mi = 0; mi < 2; mi++)
            #pragma unroll
            for (int ni = 0; ni < 4; ni++)
                #pragma unroll
                for (int q = 0; q < 4; q++) acc[mi][ni][q] = 0.f;

        float* Pb = (float*)(smc + OFF_P + (t & 1) * 34816);

        // ================= X phase (warp-private smem slice) ================
        asm volatile("cp.async.wait_group 0;\n" ::: "memory");
        {
            #pragma unroll
            for (int kc = 0; kc < 4; kc++) {
                const uint32_t bb0 = (uint32_t)(kc * 2) * 1024u;       // part 0
                const uint32_t bb1 = bb0 + 1024u;                      // part 1
                uint4 h0 = lds_u4(sXbuf + bb0 + lane * 16u);
                uint4 h1 = lds_u4(sXbuf + bb0 + 512u + lane * 16u);
                uint4 l0 = lds_u4(sXbuf + bb1 + lane * 16u);
                uint4 l1 = lds_u4(sXbuf + bb1 + 512u + lane * 16u);
                uint32_t xbH[4][2], xbL[4][2];
                xbH[0][0] = h0.x; xbH[0][1] = h0.y;
                xbH[1][0] = h0.z; xbH[1][1] = h0.w;
                xbH[2][0] = h1.x; xbH[2][1] = h1.y;
                xbH[3][0] = h1.z; xbH[3][1] = h1.w;
                xbL[0][0] = l0.x; xbL[0][1] = l0.y;
                xbL[1][0] = l0.z; xbL[1][1] = l0.w;
                xbL[2][0] = l1.x; xbL[2][1] = l1.y;
                xbL[3][0] = l1.z; xbL[3][1] = l1.w;

                uint32_t xaH[2][4], xaL[2][4];
                #pragma unroll
                for (int mi = 0; mi < 2; mi++)
                    ldsm_x4(xaH[mi], sWihH + aOffX[mi] + kc * 32);
                #pragma unroll
                for (int mi = 0; mi < 2; mi++)
                    #pragma unroll
                    for (int ni = 0; ni < 4; ni++) mma_bf16(acc[mi][ni], xaH[mi], xbH[ni]);
                #pragma unroll
                for (int mi = 0; mi < 2; mi++)
                    ldsm_x4(xaL[mi], sWihL + aOffX[mi] + kc * 32);
                #pragma unroll
                for (int mi = 0; mi < 2; mi++)
                    #pragma unroll
                    for (int ni = 0; ni < 4; ni++) mma_bf16(acc[mi][ni], xaL[mi], xbH[ni]);
                #pragma unroll
                for (int mi = 0; mi < 2; mi++)
                    #pragma unroll
                    for (int ni = 0; ni < 4; ni++) mma_bf16(acc[mi][ni], xaH[mi], xbL[ni]);
            }
        }
        // prefetch next step's slice now (LSU idle, latency hidden by H phase)
        if (t < T_STEPS - 1) xprefetch(t + 1);

        // ===== per-warp wait for its 64 producer-warp arrivals, H phase =====
        if (t > 0) {
            const unsigned long long tgt = wbase + (unsigned long long)t * 64ull;
            while (ld_acq_u64(wcnt) < tgt) { }   // all lanes spin (1 req/warp)

            const uint32_t* img = g_img[(t - 1) & 1][bh];
            uint32_t bH[4][4][2], bL[4][4][2];
            #pragma unroll
            for (int kc = 0; kc < 4; kc++) {
                const uint32_t blk = (uint32_t)(warp * 4 + kc) * 2;
                uint4 h0 = ldcg_u4(img + blk * 256 + lane * 4);
                uint4 h1 = ldcg_u4(img + blk * 256 + 128 + lane * 4);
                uint4 l0 = ldcg_u4(img + (blk + 1) * 256 + lane * 4);
                uint4 l1 = ldcg_u4(img + (blk + 1) * 256 + 128 + lane * 4);
                bH[kc][0][0] = h0.x; bH[kc][0][1] = h0.y;
                bH[kc][1][0] = h0.z; bH[kc][1][1] = h0.w;
                bH[kc][2][0] = h1.x; bH[kc][2][1] = h1.y;
                bH[kc][3][0] = h1.z; bH[kc][3][1] = h1.w;
                bL[kc][0][0] = l0.x; bL[kc][0][1] = l0.y;
                bL[kc][1][0] = l0.z; bL[kc][1][1] = l0.w;
                bL[kc][2][0] = l1.x; bL[kc][2][1] = l1.y;
                bL[kc][3][0] = l1.z; bL[kc][3][1] = l1.w;
            }
            #pragma unroll
            for (int kc = 0; kc < 4; kc++) {
                #pragma unroll
                for (int mi = 0; mi < 2; mi++)
                    #pragma unroll
                    for (int ni = 0; ni < 4; ni++) mma_bf16(acc[mi][ni], aH[kc][mi], bH[kc][ni]);
                #pragma unroll
                for (int mi = 0; mi < 2; mi++)
                    #pragma unroll
                    for (int ni = 0; ni < 4; ni++) mma_bf16(acc[mi][ni], aL[kc][mi], bH[kc][ni]);
                #pragma unroll
                for (int mi = 0; mi < 2; mi++)
                    #pragma unroll
                    for (int ni = 0; ni < 4; ni++) mma_bf16(acc[mi][ni], aH[kc][mi], bL[kc][ni]);
            }
        }

        // ================= epilogue: partials -> smem (parity) ==============
        #pragma unroll
        for (int mi = 0; mi < 2; mi++) {
            #pragma unroll
            for (int ni = 0; ni < 4; ni++) {
                const int m = mi * 16 + g;
                const int n = ni * 8 + 2 * tq;
                *(float2*)(Pb + (size_t)(warp * 32 + m) * 34 + n) =
                    make_float2(acc[mi][ni][0], acc[mi][ni][1]);
                *(float2*)(Pb + (size_t)(warp * 32 + m + 8) * 34 + n) =
                    make_float2(acc[mi][ni][2], acc[mi][ni][3]);
            }
        }
        __syncthreads();

        float h;
        {
            float gv[4];
            #pragma unroll
            for (int gate = 0; gate < 4; gate++) {
                float s = bias_s[gate * 8 + cc];
                #pragma unroll
                for (int w = 0; w < 8; w++)
                    s += Pb[(size_t)(w * 32 + gate * 8 + cc) * 34 + bb];
                gv[gate] = s;
            }
            const float ig = fast_sigmoid(gv[0]);
            const float fg = fast_sigmoid(gv[1]);
            const float gg = fast_tanh(gv[2]);
            const float og = fast_sigmoid(gv[3]);
            cst = fg * cst + ig * gg;
            h = og * fast_tanh(cst);
        }

        // publish + per-warp release (no trailing CTA barrier)
        if (t < T_STEPS - 1) {
            const float other = __shfl_xor_sync(0xffffffffu, h, 1);
            const int part = tid & 1;
            const float2 hv = part ? make_float2(other, h) : make_float2(h, other);
            const uint32_t w = part ? pack_lo2(hv) : pack_hi2(hv);
            g_img[t & 1][bh][pub_word] = w;
            __syncwarp();
            if (lane == 0) red_add_release(pcnt, 1ull);
        }

        // ys store: off the critical path
        ys[((size_t)t * 64 + bh * 32 + bb) * HID + cg * 8 + cc] = h;
    }
}

// ===========================================================================
extern "C" void kernel_launch(void* const* d_in, const int* in_sizes, int n_in,
                              void* d_out, int out_size) {
    (void)in_sizes; (void)n_in; (void)out_size;
    const float* x    = (const float*)d_in[0];
    const float* W_ih = (const float*)d_in[1];
    const float* W_hh = (const float*)d_in[2];
    const float* b_ih = (const float*)d_in[3];
    const float* b_hh = (const float*)d_in[4];
    float* ys = (float*)d_out;

    cudaFuncSetAttribute(rec_kernel, cudaFuncAttributeMaxDynamicSharedMemorySize, SMEM2);

    cvt2_kernel<<<32768, 256>>>(x);
    rec_kernel<<<REC_NCTA, 256, SMEM2>>>(W_ih, W_hh, b_ih, b_hh, ys);
}